// round 4
// baseline (speedup 1.0000x reference)
#include <cuda_runtime.h>
#include <cuda_bf16.h>

// Problem constants (from reference): B=32, T=512, D=768
#define LR_B 32
#define LR_T 512
#define LR_D 768
#define RPB 4      // source rows per scatter block
#define ZROWS 16   // output rows handled per zero-fill block

// Scratch (no cudaMalloc allowed): per-batch inclusive cumsum + totals
__device__ int g_cum[LR_B * LR_T];
__device__ int g_tot[LR_B];

// ---------------------------------------------------------------------------
// Kernel 1: per-batch rounded-duration inclusive scan.
// One warp per batch: each lane scans 16 elements in registers, then a
// 5-step shfl warp-scan combines lane totals. No __syncthreads at all.
// ---------------------------------------------------------------------------
__global__ void __launch_bounds__(32) lr_scan_kernel(const float* __restrict__ dur) {
    const int b = blockIdx.x;
    const int lane = threadIdx.x;
    const int base = b * LR_T + lane * 16;

    // Load 16 durations, round, sequential inclusive scan in registers.
    int v[16];
    int run = 0;
    #pragma unroll
    for (int i = 0; i < 16; ++i) {
        float d = __ldg(dur + base + i);
        run += (int)floorf(fmaxf(d, 0.0f) + 0.5f);
        v[i] = run;
    }

    // Exclusive warp-scan of lane totals.
    int total = run;
    int off = 0;
    #pragma unroll
    for (int s = 1; s < 32; s <<= 1) {
        int n = __shfl_up_sync(0xffffffff, total, s);
        if (lane >= s) total += n;
    }
    off = total - run;  // exclusive prefix for this lane

    #pragma unroll
    for (int i = 0; i < 16; ++i) g_cum[base + i] = v[i] + off;
    if (lane == 31) g_tot[b] = v[15] + off;
}

// ---------------------------------------------------------------------------
// Kernel 2: scatter/expand + tail zero-fill, fused into one launch.
//
// Scatter blocks (blockIdx.x < LR_T/RPB): block (g, b) owns source rows
//   s0..s0+3 (s0 = 4g). Each thread issues 4 INDEPENDENT streaming loads
//   (one float4 per row -> MLP=4), reads 5 cumsum values, then writes each
//   row reps[r] times into the contiguous output span [cum[s0-1], cum[s0+3]).
//
// Zero-fill blocks: each handles ZROWS output rows, zeroing t >= tot[b]
//   (output is 0xAA-poisoned). Most exit immediately.
// ---------------------------------------------------------------------------
__global__ void __launch_bounds__(192) lr_expand_kernel(
    const float* __restrict__ x,
    float* __restrict__ out,
    int t_out)
{
    const int b   = blockIdx.y;
    const int tid = threadIdx.x;

    if (blockIdx.x < LR_T / RPB) {
        const int s0 = blockIdx.x * RPB;

        // 4 independent streaming loads (addresses independent of cum).
        const float4* xrow = (const float4*)(x + ((size_t)b * LR_T + s0) * LR_D) + tid;
        const int stride4 = LR_D / 4;  // 192 float4s per row
        float4 v0, v1, v2, v3;
        asm volatile("ld.global.cs.v4.f32 {%0,%1,%2,%3}, [%4];"
                     : "=f"(v0.x), "=f"(v0.y), "=f"(v0.z), "=f"(v0.w)
                     : "l"(xrow));
        asm volatile("ld.global.cs.v4.f32 {%0,%1,%2,%3}, [%4];"
                     : "=f"(v1.x), "=f"(v1.y), "=f"(v1.z), "=f"(v1.w)
                     : "l"(xrow + stride4));
        asm volatile("ld.global.cs.v4.f32 {%0,%1,%2,%3}, [%4];"
                     : "=f"(v2.x), "=f"(v2.y), "=f"(v2.z), "=f"(v2.w)
                     : "l"(xrow + 2 * stride4));
        asm volatile("ld.global.cs.v4.f32 {%0,%1,%2,%3}, [%4];"
                     : "=f"(v3.x), "=f"(v3.y), "=f"(v3.z), "=f"(v3.w)
                     : "l"(xrow + 3 * stride4));

        const int* cum = g_cum + b * LR_T;
        const int prev = (s0 == 0) ? 0 : __ldg(cum + s0 - 1);
        const int c0 = __ldg(cum + s0);
        const int c1 = __ldg(cum + s0 + 1);
        const int c2 = __ldg(cum + s0 + 2);
        const int c3 = __ldg(cum + s0 + 3);
        if (c3 == prev) return;  // all four rows empty

        float4* ob = (float4*)(out + (size_t)b * t_out * LR_D) + tid;
        int t = prev;

        #pragma unroll 2
        for (; t < c0; ++t)
            asm volatile("st.global.cs.v4.f32 [%0], {%1,%2,%3,%4};"
                         :: "l"(ob + (size_t)t * stride4),
                            "f"(v0.x), "f"(v0.y), "f"(v0.z), "f"(v0.w) : "memory");
        #pragma unroll 2
        for (; t < c1; ++t)
            asm volatile("st.global.cs.v4.f32 [%0], {%1,%2,%3,%4};"
                         :: "l"(ob + (size_t)t * stride4),
                            "f"(v1.x), "f"(v1.y), "f"(v1.z), "f"(v1.w) : "memory");
        #pragma unroll 2
        for (; t < c2; ++t)
            asm volatile("st.global.cs.v4.f32 [%0], {%1,%2,%3,%4};"
                         :: "l"(ob + (size_t)t * stride4),
                            "f"(v2.x), "f"(v2.y), "f"(v2.z), "f"(v2.w) : "memory");
        #pragma unroll 2
        for (; t < c3; ++t)
            asm volatile("st.global.cs.v4.f32 [%0], {%1,%2,%3,%4};"
                         :: "l"(ob + (size_t)t * stride4),
                            "f"(v3.x), "f"(v3.y), "f"(v3.z), "f"(v3.w) : "memory");
    } else {
        // ---- zero-fill path ----
        const int tot = g_tot[b];
        const int t0  = (blockIdx.x - LR_T / RPB) * ZROWS;
        if (t0 + ZROWS <= tot) return;  // fully inside valid region

        const float4 z = make_float4(0.f, 0.f, 0.f, 0.f);
        float4* ob = (float4*)(out + (size_t)b * t_out * LR_D) + tid;
        #pragma unroll
        for (int r = 0; r < ZROWS; ++r) {
            const int t = t0 + r;
            if (t >= tot && t < t_out) {
                asm volatile("st.global.cs.v4.f32 [%0], {%1,%2,%3,%4};"
                             :: "l"(ob + (size_t)t * (LR_D / 4)),
                                "f"(z.x), "f"(z.y), "f"(z.z), "f"(z.w) : "memory");
            }
        }
    }
}

// ---------------------------------------------------------------------------
extern "C" void kernel_launch(void* const* d_in, const int* in_sizes, int n_in,
                              void* d_out, int out_size) {
    const float* x   = (const float*)d_in[0];   // [B, T, D] f32
    const float* dur = (const float*)d_in[1];   // [B, T]    f32
    float* out = (float*)d_out;                 // [B, t_out, D] f32

    const int t_out = out_size / (LR_B * LR_D);

    lr_scan_kernel<<<LR_B, 32>>>(dur);

    const int zero_blocks = (t_out + ZROWS - 1) / ZROWS;
    dim3 grid(LR_T / RPB + zero_blocks, LR_B);
    lr_expand_kernel<<<grid, 192>>>(x, out, t_out);
}